// round 12
// baseline (speedup 1.0000x reference)
#include <cuda_runtime.h>
#include <cuda_bf16.h>
#include <math.h>

// SimpleGNN, 3 launches:
//   scatter: bucket[s*CAP + atomicAdd(cursor[s],1)] = dst
//   agg:     warp per node, low-reg/no-smem (75% occ) gather -> v (tf32) -> g_vt
//   mlp:     tensor-core (tf32 mma) MLP on dense g_vt + in-kernel finalize
// Self-cleaning state (graph replays): agg re-zeros cursors hazard-free,
// mlp's last block re-zeros hsum/done.
//
// Inputs: x[N*16] f32, edge_index int32 (harness downcast), W1,b1,W2,b2,Wh,bh.
// Output: 1 f32.

#define MAX_NODES 100000
#define CAP       128
#define HID       64
#define IN_DIM    16
#define TB        128          // mlp threads per block (4 warps)
#define GRID2     592          // mlp blocks (~4/SM)
#define TILE      16           // nodes per warp-tile
#define W_STRIDE  72           // conflict-free B-frag rows (== 8 mod 32, >= 64)
#define H_STRIDE  68           // conflict-free A-frag rows (== 4 mod 32, >= 64)
#define V_STRIDE  17

__device__ unsigned g_cursor[MAX_NODES];          // zero-init at load
__device__ int      g_bucket[MAX_NODES * CAP];
__device__ unsigned g_vt[MAX_NODES * IN_DIM];     // v in tf32 bits (6.4 MB)
__device__ float    g_hsum[HID];                  // zero-init at load
__device__ unsigned g_done;                       // zero-init at load

__device__ __forceinline__ unsigned f2tf32(float f) {
    unsigned r; asm("cvt.rna.tf32.f32 %0, %1;" : "=r"(r) : "f"(f)); return r;
}

__device__ __forceinline__ void mma_tf32(float& d0, float& d1, float& d2, float& d3,
                                         unsigned a0, unsigned a1, unsigned a2, unsigned a3,
                                         unsigned b0, unsigned b1) {
    asm volatile(
        "mma.sync.aligned.m16n8k8.row.col.f32.tf32.tf32.f32 "
        "{%0,%1,%2,%3}, {%4,%5,%6,%7}, {%8,%9}, {%0,%1,%2,%3};"
        : "+f"(d0), "+f"(d1), "+f"(d2), "+f"(d3)
        : "r"(a0), "r"(a1), "r"(a2), "r"(a3), "r"(b0), "r"(b1));
}

// ---------------------------------------------------------------------------
// Scatter: 4 edges per thread; cursor atomic doubles as degree counter.
// ---------------------------------------------------------------------------
__global__ void scatter_kernel(const int* __restrict__ ei, int E, int n) {
    int t = blockIdx.x * blockDim.x + threadIdx.x;
    int base = t * 4;
    if (base >= E) return;
    int4 s4 = *(const int4*)(ei + base);
    int4 d4 = *(const int4*)(ei + E + base);
#pragma unroll
    for (int j = 0; j < 4; j++) {
        int s = (j == 0) ? s4.x : (j == 1) ? s4.y : (j == 2) ? s4.z : s4.w;
        int d = (j == 0) ? d4.x : (j == 1) ? d4.y : (j == 2) ? d4.z : d4.w;
        if ((unsigned)s < (unsigned)n) {
            unsigned slot = atomicAdd(&g_cursor[s], 1u);
            if (slot < CAP) g_bucket[(size_t)s * CAP + slot] = d;
        }
    }
}

// ---------------------------------------------------------------------------
// Aggregation: one warp per node. Minimal regs/smem -> high occupancy for
// the latency-bound gather. Writes v = x + agg/deg as tf32 bits to g_vt.
// ---------------------------------------------------------------------------
__global__ void __launch_bounds__(256) agg_kernel(const float* __restrict__ x,
                                                  int n) {
    int warp = (blockIdx.x * blockDim.x + threadIdx.x) >> 5;
    if (warp >= n) return;
    int lane = threadIdx.x & 31;
    int tg   = lane & 3;       // float4 index within a row
    int grp  = lane >> 2;      // edge group 0..7

    unsigned deg = 0u;
    if (lane == 0) {
        deg = g_cursor[warp];
        g_cursor[warp] = 0u;   // same-thread clean: program-order safe
    }
    deg = __shfl_sync(0xffffffffu, deg, 0);
    unsigned lim = (deg < CAP) ? deg : CAP;
    const int* bucket = g_bucket + (size_t)warp * CAP;

    float4 acc = make_float4(0.f, 0.f, 0.f, 0.f);
    for (unsigned i = (unsigned)grp; i < lim; i += 8) {
        int d = bucket[i];
        float4 val = ((const float4*)(x + (size_t)d * IN_DIM))[tg];
        acc.x += val.x; acc.y += val.y; acc.z += val.z; acc.w += val.w;
    }
#pragma unroll
    for (int off = 4; off < 32; off <<= 1) {
        acc.x += __shfl_xor_sync(0xffffffffu, acc.x, off);
        acc.y += __shfl_xor_sync(0xffffffffu, acc.y, off);
        acc.z += __shfl_xor_sync(0xffffffffu, acc.z, off);
        acc.w += __shfl_xor_sync(0xffffffffu, acc.w, off);
    }
    if (lane < 4) {
        float inv = 1.0f / fmaxf((float)deg, 1.0f);
        float4 xv = ((const float4*)(x + (size_t)warp * IN_DIM))[lane];
        uint4 o;
        o.x = f2tf32(xv.x + acc.x * inv);
        o.y = f2tf32(xv.y + acc.y * inv);
        o.z = f2tf32(xv.z + acc.z * inv);
        o.w = f2tf32(xv.w + acc.w * inv);
        ((uint4*)(g_vt + (size_t)warp * IN_DIM))[lane] = o;
    }
}

// ---------------------------------------------------------------------------
// MLP: tensor-core 16->64->64 on dense g_vt, hoisted A-fragments (compute-
// bound; register pressure harmless here), last-block finalize + self-clean.
// ---------------------------------------------------------------------------
__global__ void __launch_bounds__(TB) mlp_kernel(
    const float* __restrict__ W1, const float* __restrict__ b1,
    const float* __restrict__ W2, const float* __restrict__ b2,
    const float* __restrict__ Wh, const float* __restrict__ bh,
    float* __restrict__ out, int n) {
    __shared__ unsigned sW1t[IN_DIM * W_STRIDE];
    __shared__ unsigned sW2t[HID * W_STRIDE];
    __shared__ float sb1[HID];
    __shared__ float sb2[HID];
    __shared__ unsigned sv[4][TILE * V_STRIDE];
    __shared__ unsigned sh1[4][TILE * H_STRIDE];
    __shared__ float ssum[HID];
    __shared__ int slast;

    int tid  = threadIdx.x;
    int wid  = tid >> 5;
    int lane = tid & 31;
    int g    = lane >> 2;     // mma groupID (row)
    int tg   = lane & 3;      // mma threadID_in_group

    for (int i = tid; i < IN_DIM * HID; i += TB) {
        int k = i >> 6, nn = i & 63;
        sW1t[k * W_STRIDE + nn] = f2tf32(W1[i]);
    }
    for (int i = tid; i < HID * HID; i += TB) {
        int k = i >> 6, nn = i & 63;
        sW2t[k * W_STRIDE + nn] = f2tf32(W2[i]);
    }
    if (tid < HID) { sb1[tid] = b1[tid]; sb2[tid] = b2[tid]; ssum[tid] = 0.0f; }
    __syncthreads();

    unsigned* svw = sv[wid];
    unsigned* shw = sh1[wid];
    float macc[16];
#pragma unroll
    for (int i = 0; i < 16; i++) macc[i] = 0.0f;

    for (int base = (blockIdx.x * 4 + wid) * TILE; base < n;
         base += GRID2 * 4 * TILE) {

        // ---- load 16x16 v tile from g_vt (coalesced; zero-pad tail) ----
        const unsigned* src = g_vt + (size_t)base * IN_DIM;
#pragma unroll
        for (int j = 0; j < 8; j++) {
            int idx = lane * 8 + j;          // 0..255
            int nl  = idx >> 4;
            int k   = idx & 15;
            unsigned v = (base + nl < n) ? src[idx] : 0u;
            svw[nl * V_STRIDE + k] = v;
        }
        __syncwarp();

        // ---- layer 1: h1[16,64] = relu(v @ W1 + b1), hoisted A-frags ----
        unsigned a1f[2][4];
#pragma unroll
        for (int kt = 0; kt < 2; kt++) {
            int c = kt * 8 + tg;
            a1f[kt][0] = svw[g * V_STRIDE + c];
            a1f[kt][1] = svw[(g + 8) * V_STRIDE + c];
            a1f[kt][2] = svw[g * V_STRIDE + c + 4];
            a1f[kt][3] = svw[(g + 8) * V_STRIDE + c + 4];
        }
#pragma unroll
        for (int nt = 0; nt < 8; nt++) {
            int ce = nt * 8 + 2 * tg;
            float d0 = sb1[ce], d1 = sb1[ce + 1], d2 = d0, d3 = d1;
#pragma unroll
            for (int kt = 0; kt < 2; kt++) {
                unsigned bf0 = sW1t[(kt * 8 + tg) * W_STRIDE + nt * 8 + g];
                unsigned bf1 = sW1t[(kt * 8 + tg + 4) * W_STRIDE + nt * 8 + g];
                mma_tf32(d0, d1, d2, d3,
                         a1f[kt][0], a1f[kt][1], a1f[kt][2], a1f[kt][3], bf0, bf1);
            }
            shw[g * H_STRIDE + ce]           = f2tf32(fmaxf(d0, 0.0f));
            shw[g * H_STRIDE + ce + 1]       = f2tf32(fmaxf(d1, 0.0f));
            shw[(g + 8) * H_STRIDE + ce]     = f2tf32(fmaxf(d2, 0.0f));
            shw[(g + 8) * H_STRIDE + ce + 1] = f2tf32(fmaxf(d3, 0.0f));
        }
        __syncwarp();

        // ---- layer 2 + masked mean accumulation, hoisted A-frags ----
        unsigned a2f[8][4];
#pragma unroll
        for (int kt = 0; kt < 8; kt++) {
            int c = kt * 8 + tg;
            a2f[kt][0] = shw[g * H_STRIDE + c];
            a2f[kt][1] = shw[(g + 8) * H_STRIDE + c];
            a2f[kt][2] = shw[g * H_STRIDE + c + 4];
            a2f[kt][3] = shw[(g + 8) * H_STRIDE + c + 4];
        }
        float mv0 = (base + g     < n) ? 1.0f : 0.0f;
        float mv8 = (base + g + 8 < n) ? 1.0f : 0.0f;
#pragma unroll
        for (int nt = 0; nt < 8; nt++) {
            int ce = nt * 8 + 2 * tg;
            float d0 = sb2[ce], d1 = sb2[ce + 1], d2 = d0, d3 = d1;
#pragma unroll
            for (int kt = 0; kt < 8; kt++) {
                unsigned bf0 = sW2t[(kt * 8 + tg) * W_STRIDE + nt * 8 + g];
                unsigned bf1 = sW2t[(kt * 8 + tg + 4) * W_STRIDE + nt * 8 + g];
                mma_tf32(d0, d1, d2, d3,
                         a2f[kt][0], a2f[kt][1], a2f[kt][2], a2f[kt][3], bf0, bf1);
            }
            macc[2 * nt]     += mv0 * fmaxf(d0, 0.0f) + mv8 * fmaxf(d2, 0.0f);
            macc[2 * nt + 1] += mv0 * fmaxf(d1, 0.0f) + mv8 * fmaxf(d3, 0.0f);
        }
        __syncwarp();
    }

    // reduce mean partials across row-groups; lanes 0-3 hold 2 features x 8
#pragma unroll
    for (int off = 4; off < 32; off <<= 1)
#pragma unroll
        for (int i = 0; i < 16; i++)
            macc[i] += __shfl_xor_sync(0xffffffffu, macc[i], off);
    if (lane < 4) {
#pragma unroll
        for (int nt = 0; nt < 8; nt++) {
            atomicAdd(&ssum[nt * 8 + 2 * lane],     macc[2 * nt]);
            atomicAdd(&ssum[nt * 8 + 2 * lane + 1], macc[2 * nt + 1]);
        }
    }
    __syncthreads();
    if (tid < HID) atomicAdd(&g_hsum[tid], ssum[tid]);

    // ---- last-block finalize: out = tanh(mean @ Wh + bh); clean state ----
    __threadfence();
    if (tid == 0) {
        unsigned t = atomicAdd(&g_done, 1u);
        slast = (t == (unsigned)(gridDim.x - 1)) ? 1 : 0;
    }
    __syncthreads();
    if (slast) {
        __shared__ float red[HID];
        if (tid < HID) red[tid] = (g_hsum[tid] / (float)n) * Wh[tid];
        __syncthreads();
        for (int s = HID / 2; s > 0; s >>= 1) {
            if (tid < s) red[tid] += red[tid + s];
            __syncthreads();
        }
        if (tid == 0) out[0] = tanhf(red[0] + bh[0]);
        if (tid < HID) g_hsum[tid] = 0.0f;    // self-clean for next replay
        if (tid == 0) g_done = 0u;
    }
}

// ---------------------------------------------------------------------------
extern "C" void kernel_launch(void* const* d_in, const int* in_sizes, int n_in,
                              void* d_out, int out_size) {
    const float* x  = (const float*)d_in[0];
    const int*   ei = (const int*)d_in[1];
    const float* W1 = (const float*)d_in[2];
    const float* b1 = (const float*)d_in[3];
    const float* W2 = (const float*)d_in[4];
    const float* b2 = (const float*)d_in[5];
    const float* Wh = (const float*)d_in[6];
    const float* bh = (const float*)d_in[7];
    float* out = (float*)d_out;

    int n = in_sizes[0] / IN_DIM;
    int E = in_sizes[1] / 2;
    int et = (E + 3) / 4;
    int ab = (n * 32 + 255) / 256;   // agg: one warp per node

    scatter_kernel<<<(et + 255) / 256, 256>>>(ei, E, n);
    agg_kernel<<<ab, 256>>>(x, n);
    mlp_kernel<<<GRID2, TB>>>(W1, b1, W2, b2, Wh, bh, out, n);
}

// round 13
// speedup vs baseline: 2.4319x; 2.4319x over previous
#include <cuda_runtime.h>
#include <cuda_bf16.h>
#include <math.h>

// SimpleGNN: bucket scatter + tensor-core (tf32 mma) fused agg/MLP with
// in-kernel finalize. 2 launches (round-10 champion structure).
// This round: software-pipelined gather — the per-node degree loop runs in
// fixed chunks of 8 iterations/lane (all bucket index loads issued first,
// then all x gathers, adds predicated) so ptxas can keep ~8 loads in
// flight instead of one serial bucket->x chain per iteration.
//
// Inputs: x[N*16] f32, edge_index int32 (harness downcast), W1,b1,W2,b2,Wh,bh.
// Output: 1 f32.

#define MAX_NODES 100000
#define CAP       128
#define HID       64
#define IN_DIM    16
#define TB        128          // threads per block (4 warps)
#define GRID_BLOCKS 592        // ~4 blocks/SM
#define TILE      16           // nodes per warp-tile
#define CHUNK     8            // gather iterations batched per lane
#define W_STRIDE  72           // conflict-free B-frag rows
#define H_STRIDE  68
#define V_STRIDE  17

__device__ unsigned g_cursor[MAX_NODES];          // zero-init at load
__device__ int      g_bucket[MAX_NODES * CAP];
__device__ float    g_hsum[HID];                  // zero-init at load
__device__ unsigned g_done;                       // zero-init at load

__device__ __forceinline__ unsigned f2tf32(float f) {
    unsigned r; asm("cvt.rna.tf32.f32 %0, %1;" : "=r"(r) : "f"(f)); return r;
}

__device__ __forceinline__ void mma_tf32(float& d0, float& d1, float& d2, float& d3,
                                         unsigned a0, unsigned a1, unsigned a2, unsigned a3,
                                         unsigned b0, unsigned b1) {
    asm volatile(
        "mma.sync.aligned.m16n8k8.row.col.f32.tf32.tf32.f32 "
        "{%0,%1,%2,%3}, {%4,%5,%6,%7}, {%8,%9}, {%0,%1,%2,%3};"
        : "+f"(d0), "+f"(d1), "+f"(d2), "+f"(d3)
        : "r"(a0), "r"(a1), "r"(a2), "r"(a3), "r"(b0), "r"(b1));
}

// ---------------------------------------------------------------------------
// Scatter: 4 edges per thread; cursor atomic doubles as degree counter.
// ---------------------------------------------------------------------------
__global__ void scatter_kernel(const int* __restrict__ ei, int E, int n) {
    int t = blockIdx.x * blockDim.x + threadIdx.x;
    int base = t * 4;
    if (base >= E) return;
    int4 s4 = *(const int4*)(ei + base);
    int4 d4 = *(const int4*)(ei + E + base);
#pragma unroll
    for (int j = 0; j < 4; j++) {
        int s = (j == 0) ? s4.x : (j == 1) ? s4.y : (j == 2) ? s4.z : s4.w;
        int d = (j == 0) ? d4.x : (j == 1) ? d4.y : (j == 2) ? d4.z : d4.w;
        if ((unsigned)s < (unsigned)n) {
            unsigned slot = atomicAdd(&g_cursor[s], 1u);
            if (slot < CAP) g_bucket[(size_t)s * CAP + slot] = d;
        }
    }
}

// ---------------------------------------------------------------------------
// Fused aggregation + MMA MLP + last-block finalize + self-clean.
// ---------------------------------------------------------------------------
__global__ void __launch_bounds__(TB, 4) fused_kernel(
    const float* __restrict__ x,
    const float* __restrict__ W1, const float* __restrict__ b1,
    const float* __restrict__ W2, const float* __restrict__ b2,
    const float* __restrict__ Wh, const float* __restrict__ bh,
    float* __restrict__ out, int n) {
    __shared__ unsigned sW1t[IN_DIM * W_STRIDE];
    __shared__ unsigned sW2t[HID * W_STRIDE];
    __shared__ float sb1[HID];
    __shared__ float sb2[HID];
    __shared__ unsigned sv[4][TILE * V_STRIDE];
    __shared__ unsigned sh1[4][TILE * H_STRIDE];
    __shared__ float ssum[HID];
    __shared__ int slast;

    int tid  = threadIdx.x;
    int wid  = tid >> 5;
    int lane = tid & 31;
    int g    = lane >> 2;     // mma groupID (row) / edge group
    int tg   = lane & 3;      // mma threadID_in_group / float4 index

    for (int i = tid; i < IN_DIM * HID; i += TB) {
        int k = i >> 6, nn = i & 63;
        sW1t[k * W_STRIDE + nn] = f2tf32(W1[i]);
    }
    for (int i = tid; i < HID * HID; i += TB) {
        int k = i >> 6, nn = i & 63;
        sW2t[k * W_STRIDE + nn] = f2tf32(W2[i]);
    }
    if (tid < HID) { sb1[tid] = b1[tid]; sb2[tid] = b2[tid]; ssum[tid] = 0.0f; }
    __syncthreads();

    unsigned* svw = sv[wid];
    unsigned* shw = sh1[wid];
    float macc[16];
#pragma unroll
    for (int i = 0; i < 16; i++) macc[i] = 0.0f;

    for (int base = (blockIdx.x * 4 + wid) * TILE; base < n;
         base += GRID_BLOCKS * 4 * TILE) {

        // ---- batched degree load + same-thread clean (hazard-free) ----
        unsigned mydeg = 0u;
        if (lane < TILE && base + lane < n) {
            mydeg = g_cursor[base + lane];       // one coalesced 64B load
            g_cursor[base + lane] = 0u;          // program-order safe
        }
        __syncwarp();

        // ---- aggregate 16 nodes: software-pipelined chunked gather ----
        for (int nl = 0; nl < TILE; nl++) {
            int node = base + nl;
            unsigned deg = __shfl_sync(0xffffffffu, mydeg, nl);
            if (node < n) {
                unsigned lim = (deg < CAP) ? deg : CAP;
                const int* bucket = g_bucket + (size_t)node * CAP;
                float4 acc = make_float4(0.f, 0.f, 0.f, 0.f);
                // chunks of CHUNK iterations per lane (CHUNK*8 edges);
                // deg ~ Poisson(32) => one chunk for virtually all nodes
                for (unsigned ib = 0; ib < lim; ib += CHUNK * 8) {
                    int dd[CHUNK];
#pragma unroll
                    for (int u = 0; u < CHUNK; u++) {
                        unsigned i = ib + (unsigned)(u * 8 + g);
                        dd[u] = bucket[(i < lim) ? i : 0];   // clamped addr,
                    }                                        // loads batched
#pragma unroll
                    for (int u = 0; u < CHUNK; u++) {
                        unsigned i = ib + (unsigned)(u * 8 + g);
                        float4 val = ((const float4*)(x + (size_t)dd[u] * IN_DIM))[tg];
                        if (i < lim) {                       // predicated add
                            acc.x += val.x; acc.y += val.y;
                            acc.z += val.z; acc.w += val.w;
                        }
                    }
                }
#pragma unroll
                for (int off = 4; off < 32; off <<= 1) {
                    acc.x += __shfl_xor_sync(0xffffffffu, acc.x, off);
                    acc.y += __shfl_xor_sync(0xffffffffu, acc.y, off);
                    acc.z += __shfl_xor_sync(0xffffffffu, acc.z, off);
                    acc.w += __shfl_xor_sync(0xffffffffu, acc.w, off);
                }
                if (lane < 4) {
                    float inv = 1.0f / fmaxf((float)deg, 1.0f);
                    float4 xv = ((const float4*)(x + (size_t)node * IN_DIM))[lane];
                    unsigned* vp = svw + nl * V_STRIDE + lane * 4;
                    vp[0] = f2tf32(xv.x + acc.x * inv);
                    vp[1] = f2tf32(xv.y + acc.y * inv);
                    vp[2] = f2tf32(xv.z + acc.z * inv);
                    vp[3] = f2tf32(xv.w + acc.w * inv);
                }
            } else if (lane < 4) {
                unsigned* vp = svw + nl * V_STRIDE + lane * 4;
                vp[0] = vp[1] = vp[2] = vp[3] = 0u;
            }
        }
        __syncwarp();

        // ---- layer 1: h1[16,64] = relu(v @ W1 + b1), hoisted A-frags ----
        unsigned a1f[2][4];
#pragma unroll
        for (int kt = 0; kt < 2; kt++) {
            int c = kt * 8 + tg;
            a1f[kt][0] = svw[g * V_STRIDE + c];
            a1f[kt][1] = svw[(g + 8) * V_STRIDE + c];
            a1f[kt][2] = svw[g * V_STRIDE + c + 4];
            a1f[kt][3] = svw[(g + 8) * V_STRIDE + c + 4];
        }
#pragma unroll
        for (int nt = 0; nt < 8; nt++) {
            int ce = nt * 8 + 2 * tg;
            float d0 = sb1[ce], d1 = sb1[ce + 1], d2 = d0, d3 = d1;
#pragma unroll
            for (int kt = 0; kt < 2; kt++) {
                unsigned bf0 = sW1t[(kt * 8 + tg) * W_STRIDE + nt * 8 + g];
                unsigned bf1 = sW1t[(kt * 8 + tg + 4) * W_STRIDE + nt * 8 + g];
                mma_tf32(d0, d1, d2, d3,
                         a1f[kt][0], a1f[kt][1], a1f[kt][2], a1f[kt][3], bf0, bf1);
            }
            shw[g * H_STRIDE + ce]           = f2tf32(fmaxf(d0, 0.0f));
            shw[g * H_STRIDE + ce + 1]       = f2tf32(fmaxf(d1, 0.0f));
            shw[(g + 8) * H_STRIDE + ce]     = f2tf32(fmaxf(d2, 0.0f));
            shw[(g + 8) * H_STRIDE + ce + 1] = f2tf32(fmaxf(d3, 0.0f));
        }
        __syncwarp();

        // ---- layer 2 + masked mean accumulation, hoisted A-frags ----
        unsigned a2f[8][4];
#pragma unroll
        for (int kt = 0; kt < 8; kt++) {
            int c = kt * 8 + tg;
            a2f[kt][0] = shw[g * H_STRIDE + c];
            a2f[kt][1] = shw[(g + 8) * H_STRIDE + c];
            a2f[kt][2] = shw[g * H_STRIDE + c + 4];
            a2f[kt][3] = shw[(g + 8) * H_STRIDE + c + 4];
        }
        float mv0 = (base + g     < n) ? 1.0f : 0.0f;
        float mv8 = (base + g + 8 < n) ? 1.0f : 0.0f;
#pragma unroll
        for (int nt = 0; nt < 8; nt++) {
            int ce = nt * 8 + 2 * tg;
            float d0 = sb2[ce], d1 = sb2[ce + 1], d2 = d0, d3 = d1;
#pragma unroll
            for (int kt = 0; kt < 8; kt++) {
                unsigned bf0 = sW2t[(kt * 8 + tg) * W_STRIDE + nt * 8 + g];
                unsigned bf1 = sW2t[(kt * 8 + tg + 4) * W_STRIDE + nt * 8 + g];
                mma_tf32(d0, d1, d2, d3,
                         a2f[kt][0], a2f[kt][1], a2f[kt][2], a2f[kt][3], bf0, bf1);
            }
            macc[2 * nt]     += mv0 * fmaxf(d0, 0.0f) + mv8 * fmaxf(d2, 0.0f);
            macc[2 * nt + 1] += mv0 * fmaxf(d1, 0.0f) + mv8 * fmaxf(d3, 0.0f);
        }
        __syncwarp();
    }

    // reduce mean partials across row-groups; lanes 0-3 hold 2 features x 8
#pragma unroll
    for (int off = 4; off < 32; off <<= 1)
#pragma unroll
        for (int i = 0; i < 16; i++)
            macc[i] += __shfl_xor_sync(0xffffffffu, macc[i], off);
    if (lane < 4) {
#pragma unroll
        for (int nt = 0; nt < 8; nt++) {
            atomicAdd(&ssum[nt * 8 + 2 * lane],     macc[2 * nt]);
            atomicAdd(&ssum[nt * 8 + 2 * lane + 1], macc[2 * nt + 1]);
        }
    }
    __syncthreads();
    if (tid < HID) atomicAdd(&g_hsum[tid], ssum[tid]);

    // ---- last-block finalize: out = tanh(mean @ Wh + bh); clean state ----
    __threadfence();
    if (tid == 0) {
        unsigned t = atomicAdd(&g_done, 1u);
        slast = (t == (unsigned)(gridDim.x - 1)) ? 1 : 0;
    }
    __syncthreads();
    if (slast) {
        __shared__ float red[HID];
        if (tid < HID) red[tid] = (g_hsum[tid] / (float)n) * Wh[tid];
        __syncthreads();
        for (int s = HID / 2; s > 0; s >>= 1) {
            if (tid < s) red[tid] += red[tid + s];
            __syncthreads();
        }
        if (tid == 0) out[0] = tanhf(red[0] + bh[0]);
        if (tid < HID) g_hsum[tid] = 0.0f;    // self-clean for next replay
        if (tid == 0) g_done = 0u;
    }
}

// ---------------------------------------------------------------------------
extern "C" void kernel_launch(void* const* d_in, const int* in_sizes, int n_in,
                              void* d_out, int out_size) {
    const float* x  = (const float*)d_in[0];
    const int*   ei = (const int*)d_in[1];
    const float* W1 = (const float*)d_in[2];
    const float* b1 = (const float*)d_in[3];
    const float* W2 = (const float*)d_in[4];
    const float* b2 = (const float*)d_in[5];
    const float* Wh = (const float*)d_in[6];
    const float* bh = (const float*)d_in[7];
    float* out = (float*)d_out;

    int n = in_sizes[0] / IN_DIM;
    int E = in_sizes[1] / 2;
    int et = (E + 3) / 4;

    scatter_kernel<<<(et + 255) / 256, 256>>>(ei, E, n);
    fused_kernel<<<GRID_BLOCKS, TB>>>(x, W1, b1, W2, b2, Wh, bh, out, n);
}

// round 14
// speedup vs baseline: 2.6253x; 1.0795x over previous
#include <cuda_runtime.h>
#include <cuda_bf16.h>
#include <math.h>

// SimpleGNN, 3 launches (split v2):
//   scatter: bucket[s*CAP + atomicAdd(cursor[s],1)] = dst
//   agg:     16 nodes/warp chunk-8 pipelined gather (R13-proven inner loop)
//            in a no-smem low-reg kernel (32-40 warps/SM) -> g_vt (tf32 bits)
//   mlp:     tensor-core (tf32 mma) MLP on dense g_vt + in-kernel finalize
// Self-cleaning for graph replays: agg re-zeros cursors (hazard-free same-
// thread pattern), mlp's last block re-zeros hsum/done.
//
// Inputs: x[N*16] f32, edge_index int32 (harness downcast), W1,b1,W2,b2,Wh,bh.
// Output: 1 f32.

#define MAX_NODES 100000
#define CAP       128
#define HID       64
#define IN_DIM    16
#define TILE      16           // nodes per warp-tile
#define CHUNK     8            // gather iterations batched per lane
#define AGG_TB    256          // agg threads per block (8 warps)
#define TB        128          // mlp threads per block (4 warps)
#define GRID2     592          // mlp blocks (~4/SM)
#define W_STRIDE  72           // conflict-free B-frag rows
#define H_STRIDE  68
#define V_STRIDE  17

__device__ unsigned g_cursor[MAX_NODES];          // zero-init at load
__device__ int      g_bucket[MAX_NODES * CAP];
__device__ unsigned g_vt[MAX_NODES * IN_DIM];     // v in tf32 bits (6.4 MB)
__device__ float    g_hsum[HID];                  // zero-init at load
__device__ unsigned g_done;                       // zero-init at load

__device__ __forceinline__ unsigned f2tf32(float f) {
    unsigned r; asm("cvt.rna.tf32.f32 %0, %1;" : "=r"(r) : "f"(f)); return r;
}

__device__ __forceinline__ void mma_tf32(float& d0, float& d1, float& d2, float& d3,
                                         unsigned a0, unsigned a1, unsigned a2, unsigned a3,
                                         unsigned b0, unsigned b1) {
    asm volatile(
        "mma.sync.aligned.m16n8k8.row.col.f32.tf32.tf32.f32 "
        "{%0,%1,%2,%3}, {%4,%5,%6,%7}, {%8,%9}, {%0,%1,%2,%3};"
        : "+f"(d0), "+f"(d1), "+f"(d2), "+f"(d3)
        : "r"(a0), "r"(a1), "r"(a2), "r"(a3), "r"(b0), "r"(b1));
}

// ---------------------------------------------------------------------------
// Scatter: 4 edges per thread; cursor atomic doubles as degree counter.
// ---------------------------------------------------------------------------
__global__ void scatter_kernel(const int* __restrict__ ei, int E, int n) {
    int t = blockIdx.x * blockDim.x + threadIdx.x;
    int base = t * 4;
    if (base >= E) return;
    int4 s4 = *(const int4*)(ei + base);
    int4 d4 = *(const int4*)(ei + E + base);
#pragma unroll
    for (int j = 0; j < 4; j++) {
        int s = (j == 0) ? s4.x : (j == 1) ? s4.y : (j == 2) ? s4.z : s4.w;
        int d = (j == 0) ? d4.x : (j == 1) ? d4.y : (j == 2) ? d4.z : d4.w;
        if ((unsigned)s < (unsigned)n) {
            unsigned slot = atomicAdd(&g_cursor[s], 1u);
            if (slot < CAP) g_bucket[(size_t)s * CAP + slot] = d;
        }
    }
}

// ---------------------------------------------------------------------------
// Aggregation: 16 nodes per warp, chunk-8 software-pipelined gather.
// No smem, low regs -> high occupancy for the latency-bound phase.
// Writes v = x + agg/deg as tf32 bits to g_vt.
// ---------------------------------------------------------------------------
__global__ void __launch_bounds__(AGG_TB, 4) agg_kernel(
    const float* __restrict__ x, int n) {
    int wid  = threadIdx.x >> 5;
    int lane = threadIdx.x & 31;
    int g    = lane >> 2;      // edge group 0..7
    int tg   = lane & 3;       // float4 index within a row

    int base = (blockIdx.x * 8 + wid) * TILE;
    if (base >= n) return;

    // batched degree load + same-thread clean (hazard-free)
    unsigned mydeg = 0u;
    if (lane < TILE && base + lane < n) {
        mydeg = g_cursor[base + lane];
        g_cursor[base + lane] = 0u;        // program-order safe
    }
    __syncwarp();

    for (int nl = 0; nl < TILE; nl++) {
        int node = base + nl;
        if (node >= n) break;
        unsigned deg = __shfl_sync(0xffffffffu, mydeg, nl);
        unsigned lim = (deg < CAP) ? deg : CAP;
        const int* bucket = g_bucket + (size_t)node * CAP;
        float4 acc = make_float4(0.f, 0.f, 0.f, 0.f);
        for (unsigned ib = 0; ib < lim; ib += CHUNK * 8) {
            int dd[CHUNK];
#pragma unroll
            for (int u = 0; u < CHUNK; u++) {
                unsigned i = ib + (unsigned)(u * 8 + g);
                dd[u] = bucket[(i < lim) ? i : 0];   // clamped addr, batched
            }
#pragma unroll
            for (int u = 0; u < CHUNK; u++) {
                unsigned i = ib + (unsigned)(u * 8 + g);
                float4 val = ((const float4*)(x + (size_t)dd[u] * IN_DIM))[tg];
                if (i < lim) {                       // predicated add
                    acc.x += val.x; acc.y += val.y;
                    acc.z += val.z; acc.w += val.w;
                }
            }
        }
#pragma unroll
        for (int off = 4; off < 32; off <<= 1) {
            acc.x += __shfl_xor_sync(0xffffffffu, acc.x, off);
            acc.y += __shfl_xor_sync(0xffffffffu, acc.y, off);
            acc.z += __shfl_xor_sync(0xffffffffu, acc.z, off);
            acc.w += __shfl_xor_sync(0xffffffffu, acc.w, off);
        }
        if (lane < 4) {
            float inv = 1.0f / fmaxf((float)deg, 1.0f);
            float4 xv = ((const float4*)(x + (size_t)node * IN_DIM))[lane];
            uint4 o;
            o.x = f2tf32(xv.x + acc.x * inv);
            o.y = f2tf32(xv.y + acc.y * inv);
            o.z = f2tf32(xv.z + acc.z * inv);
            o.w = f2tf32(xv.w + acc.w * inv);
            ((uint4*)(g_vt + (size_t)node * IN_DIM))[lane] = o;
        }
    }
}

// ---------------------------------------------------------------------------
// MLP: tensor-core 16->64->64 on dense g_vt, hoisted A-fragments,
// last-block finalize + self-clean.
// ---------------------------------------------------------------------------
__global__ void __launch_bounds__(TB) mlp_kernel(
    const float* __restrict__ W1, const float* __restrict__ b1,
    const float* __restrict__ W2, const float* __restrict__ b2,
    const float* __restrict__ Wh, const float* __restrict__ bh,
    float* __restrict__ out, int n) {
    __shared__ unsigned sW1t[IN_DIM * W_STRIDE];
    __shared__ unsigned sW2t[HID * W_STRIDE];
    __shared__ float sb1[HID];
    __shared__ float sb2[HID];
    __shared__ unsigned sv[4][TILE * V_STRIDE];
    __shared__ unsigned sh1[4][TILE * H_STRIDE];
    __shared__ float ssum[HID];
    __shared__ int slast;

    int tid  = threadIdx.x;
    int wid  = tid >> 5;
    int lane = tid & 31;
    int g    = lane >> 2;     // mma groupID (row)
    int tg   = lane & 3;      // mma threadID_in_group

    for (int i = tid; i < IN_DIM * HID; i += TB) {
        int k = i >> 6, nn = i & 63;
        sW1t[k * W_STRIDE + nn] = f2tf32(W1[i]);
    }
    for (int i = tid; i < HID * HID; i += TB) {
        int k = i >> 6, nn = i & 63;
        sW2t[k * W_STRIDE + nn] = f2tf32(W2[i]);
    }
    if (tid < HID) { sb1[tid] = b1[tid]; sb2[tid] = b2[tid]; ssum[tid] = 0.0f; }
    __syncthreads();

    unsigned* svw = sv[wid];
    unsigned* shw = sh1[wid];
    float macc[16];
#pragma unroll
    for (int i = 0; i < 16; i++) macc[i] = 0.0f;

    for (int base = (blockIdx.x * 4 + wid) * TILE; base < n;
         base += GRID2 * 4 * TILE) {

        // ---- load 16x16 v tile from g_vt (coalesced; zero-pad tail) ----
        const unsigned* src = g_vt + (size_t)base * IN_DIM;
#pragma unroll
        for (int j = 0; j < 8; j++) {
            int idx = lane * 8 + j;          // 0..255
            int nl  = idx >> 4;
            int k   = idx & 15;
            unsigned v = (base + nl < n) ? src[idx] : 0u;
            svw[nl * V_STRIDE + k] = v;
        }
        __syncwarp();

        // ---- layer 1: h1[16,64] = relu(v @ W1 + b1), hoisted A-frags ----
        unsigned a1f[2][4];
#pragma unroll
        for (int kt = 0; kt < 2; kt++) {
            int c = kt * 8 + tg;
            a1f[kt][0] = svw[g * V_STRIDE + c];
            a1f[kt][1] = svw[(g + 8) * V_STRIDE + c];
            a1f[kt][2] = svw[g * V_STRIDE + c + 4];
            a1f[kt][3] = svw[(g + 8) * V_STRIDE + c + 4];
        }
#pragma unroll
        for (int nt = 0; nt < 8; nt++) {
            int ce = nt * 8 + 2 * tg;
            float d0 = sb1[ce], d1 = sb1[ce + 1], d2 = d0, d3 = d1;
#pragma unroll
            for (int kt = 0; kt < 2; kt++) {
                unsigned bf0 = sW1t[(kt * 8 + tg) * W_STRIDE + nt * 8 + g];
                unsigned bf1 = sW1t[(kt * 8 + tg + 4) * W_STRIDE + nt * 8 + g];
                mma_tf32(d0, d1, d2, d3,
                         a1f[kt][0], a1f[kt][1], a1f[kt][2], a1f[kt][3], bf0, bf1);
            }
            shw[g * H_STRIDE + ce]           = f2tf32(fmaxf(d0, 0.0f));
            shw[g * H_STRIDE + ce + 1]       = f2tf32(fmaxf(d1, 0.0f));
            shw[(g + 8) * H_STRIDE + ce]     = f2tf32(fmaxf(d2, 0.0f));
            shw[(g + 8) * H_STRIDE + ce + 1] = f2tf32(fmaxf(d3, 0.0f));
        }
        __syncwarp();

        // ---- layer 2 + masked mean accumulation, hoisted A-frags ----
        unsigned a2f[8][4];
#pragma unroll
        for (int kt = 0; kt < 8; kt++) {
            int c = kt * 8 + tg;
            a2f[kt][0] = shw[g * H_STRIDE + c];
            a2f[kt][1] = shw[(g + 8) * H_STRIDE + c];
            a2f[kt][2] = shw[g * H_STRIDE + c + 4];
            a2f[kt][3] = shw[(g + 8) * H_STRIDE + c + 4];
        }
        float mv0 = (base + g     < n) ? 1.0f : 0.0f;
        float mv8 = (base + g + 8 < n) ? 1.0f : 0.0f;
#pragma unroll
        for (int nt = 0; nt < 8; nt++) {
            int ce = nt * 8 + 2 * tg;
            float d0 = sb2[ce], d1 = sb2[ce + 1], d2 = d0, d3 = d1;
#pragma unroll
            for (int kt = 0; kt < 8; kt++) {
                unsigned bf0 = sW2t[(kt * 8 + tg) * W_STRIDE + nt * 8 + g];
                unsigned bf1 = sW2t[(kt * 8 + tg + 4) * W_STRIDE + nt * 8 + g];
                mma_tf32(d0, d1, d2, d3,
                         a2f[kt][0], a2f[kt][1], a2f[kt][2], a2f[kt][3], bf0, bf1);
            }
            macc[2 * nt]     += mv0 * fmaxf(d0, 0.0f) + mv8 * fmaxf(d2, 0.0f);
            macc[2 * nt + 1] += mv0 * fmaxf(d1, 0.0f) + mv8 * fmaxf(d3, 0.0f);
        }
        __syncwarp();
    }

    // reduce mean partials across row-groups; lanes 0-3 hold 2 features x 8
#pragma unroll
    for (int off = 4; off < 32; off <<= 1)
#pragma unroll
        for (int i = 0; i < 16; i++)
            macc[i] += __shfl_xor_sync(0xffffffffu, macc[i], off);
    if (lane < 4) {
#pragma unroll
        for (int nt = 0; nt < 8; nt++) {
            atomicAdd(&ssum[nt * 8 + 2 * lane],     macc[2 * nt]);
            atomicAdd(&ssum[nt * 8 + 2 * lane + 1], macc[2 * nt + 1]);
        }
    }
    __syncthreads();
    if (tid < HID) atomicAdd(&g_hsum[tid], ssum[tid]);

    // ---- last-block finalize: out = tanh(mean @ Wh + bh); clean state ----
    __threadfence();
    if (tid == 0) {
        unsigned t = atomicAdd(&g_done, 1u);
        slast = (t == (unsigned)(gridDim.x - 1)) ? 1 : 0;
    }
    __syncthreads();
    if (slast) {
        __shared__ float red[HID];
        if (tid < HID) red[tid] = (g_hsum[tid] / (float)n) * Wh[tid];
        __syncthreads();
        for (int s = HID / 2; s > 0; s >>= 1) {
            if (tid < s) red[tid] += red[tid + s];
            __syncthreads();
        }
        if (tid == 0) out[0] = tanhf(red[0] + bh[0]);
        if (tid < HID) g_hsum[tid] = 0.0f;    // self-clean for next replay
        if (tid == 0) g_done = 0u;
    }
}

// ---------------------------------------------------------------------------
extern "C" void kernel_launch(void* const* d_in, const int* in_sizes, int n_in,
                              void* d_out, int out_size) {
    const float* x  = (const float*)d_in[0];
    const int*   ei = (const int*)d_in[1];
    const float* W1 = (const float*)d_in[2];
    const float* b1 = (const float*)d_in[3];
    const float* W2 = (const float*)d_in[4];
    const float* b2 = (const float*)d_in[5];
    const float* Wh = (const float*)d_in[6];
    const float* bh = (const float*)d_in[7];
    float* out = (float*)d_out;

    int n = in_sizes[0] / IN_DIM;
    int E = in_sizes[1] / 2;
    int et = (E + 3) / 4;
    int ab = (n + 8 * TILE - 1) / (8 * TILE);   // agg: 8 warps x 16 nodes

    scatter_kernel<<<(et + 255) / 256, 256>>>(ei, E, n);
    agg_kernel<<<ab, AGG_TB>>>(x, n);
    mlp_kernel<<<GRID2, TB>>>(W1, b1, W2, b2, Wh, bh, out, n);
}

// round 15
// speedup vs baseline: 2.6553x; 1.0114x over previous
#include <cuda_runtime.h>
#include <cuda_bf16.h>
#include <cuda_fp16.h>
#include <math.h>

// SimpleGNN, 3 launches:
//   scatter: bucket[s*CAP + atomicAdd(cursor[s],1)] = dst; ALSO converts x to
//            an fp16 table g_xh (same threads, L2-bound kernel, ~free)
//   agg:     16 nodes/warp chunk-8 pipelined gather from g_xh (1 sector/row:
//            lane reads 8B via one LDG.64) -> g_vt (tf32 bits)
//   mlp:     tensor-core (tf32 mma) MLP on dense g_vt + in-kernel finalize
// Self-cleaning for graph replays: agg re-zeros cursors (hazard-free same-
// thread pattern), mlp's last block re-zeros hsum/done.
//
// Inputs: x[N*16] f32, edge_index int32 (harness downcast), W1,b1,W2,b2,Wh,bh.
// Output: 1 f32.

#define MAX_NODES 100000
#define CAP       128
#define HID       64
#define IN_DIM    16
#define TILE      16           // nodes per warp-tile
#define CHUNK     8            // gather iterations batched per lane
#define AGG_TB    256          // agg threads per block (8 warps)
#define TB        128          // mlp threads per block (4 warps)
#define GRID2     592          // mlp blocks (~4/SM)
#define W_STRIDE  72           // conflict-free B-frag rows
#define H_STRIDE  68
#define V_STRIDE  17

__device__ unsigned g_cursor[MAX_NODES];          // zero-init at load
__device__ int      g_bucket[MAX_NODES * CAP];
__device__ __half   g_xh[MAX_NODES * IN_DIM];     // fp16 x table (3.2 MB)
__device__ unsigned g_vt[MAX_NODES * IN_DIM];     // v in tf32 bits (6.4 MB)
__device__ float    g_hsum[HID];                  // zero-init at load
__device__ unsigned g_done;                       // zero-init at load

__device__ __forceinline__ unsigned f2tf32(float f) {
    unsigned r; asm("cvt.rna.tf32.f32 %0, %1;" : "=r"(r) : "f"(f)); return r;
}

__device__ __forceinline__ void mma_tf32(float& d0, float& d1, float& d2, float& d3,
                                         unsigned a0, unsigned a1, unsigned a2, unsigned a3,
                                         unsigned b0, unsigned b1) {
    asm volatile(
        "mma.sync.aligned.m16n8k8.row.col.f32.tf32.tf32.f32 "
        "{%0,%1,%2,%3}, {%4,%5,%6,%7}, {%8,%9}, {%0,%1,%2,%3};"
        : "+f"(d0), "+f"(d1), "+f"(d2), "+f"(d3)
        : "r"(a0), "r"(a1), "r"(a2), "r"(a3), "r"(b0), "r"(b1));
}

// ---------------------------------------------------------------------------
// Scatter + x->fp16 conversion. 4 edges per thread; cursor atomic doubles as
// degree counter. Thread t also converts half2 word t (t < n*8 exactly
// matches the 800k-thread grid at E=3.2M).
// ---------------------------------------------------------------------------
__global__ void scatter_kernel(const int* __restrict__ ei,
                               const float* __restrict__ x, int E, int n) {
    int t = blockIdx.x * blockDim.x + threadIdx.x;

    // fp16 table build (coalesced, independent of edge work)
    int nh2 = n * (IN_DIM / 2);
    if (t < nh2) {
        float2 f = ((const float2*)x)[t];
        ((half2*)g_xh)[t] = __floats2half2_rn(f.x, f.y);
    }

    int base = t * 4;
    if (base >= E) return;
    int4 s4 = *(const int4*)(ei + base);
    int4 d4 = *(const int4*)(ei + E + base);
#pragma unroll
    for (int j = 0; j < 4; j++) {
        int s = (j == 0) ? s4.x : (j == 1) ? s4.y : (j == 2) ? s4.z : s4.w;
        int d = (j == 0) ? d4.x : (j == 1) ? d4.y : (j == 2) ? d4.z : d4.w;
        if ((unsigned)s < (unsigned)n) {
            unsigned slot = atomicAdd(&g_cursor[s], 1u);
            if (slot < CAP) g_bucket[(size_t)s * CAP + slot] = d;
        }
    }
}

// ---------------------------------------------------------------------------
// Aggregation: 16 nodes per warp, chunk-8 software-pipelined gather from the
// fp16 table (one LDG.64 per edge-lane; 8 rows x 1 sector per warp instr).
// Writes v = x + agg/deg as tf32 bits to g_vt.
// ---------------------------------------------------------------------------
__global__ void __launch_bounds__(AGG_TB, 4) agg_kernel(
    const float* __restrict__ x, int n) {
    int wid  = threadIdx.x >> 5;
    int lane = threadIdx.x & 31;
    int g    = lane >> 2;      // edge group 0..7
    int tg   = lane & 3;       // quarter-row index (4 halves = 8B)

    int base = (blockIdx.x * 8 + wid) * TILE;
    if (base >= n) return;

    // batched degree load + same-thread clean (hazard-free)
    unsigned mydeg = 0u;
    if (lane < TILE && base + lane < n) {
        mydeg = g_cursor[base + lane];
        g_cursor[base + lane] = 0u;        // program-order safe
    }
    __syncwarp();

    for (int nl = 0; nl < TILE; nl++) {
        int node = base + nl;
        if (node >= n) break;
        unsigned deg = __shfl_sync(0xffffffffu, mydeg, nl);
        unsigned lim = (deg < CAP) ? deg : CAP;
        const int* bucket = g_bucket + (size_t)node * CAP;
        float4 acc = make_float4(0.f, 0.f, 0.f, 0.f);
        for (unsigned ib = 0; ib < lim; ib += CHUNK * 8) {
            int dd[CHUNK];
#pragma unroll
            for (int u = 0; u < CHUNK; u++) {
                unsigned i = ib + (unsigned)(u * 8 + g);
                dd[u] = bucket[(i < lim) ? i : 0];   // clamped addr, batched
            }
#pragma unroll
            for (int u = 0; u < CHUNK; u++) {
                unsigned i = ib + (unsigned)(u * 8 + g);
                // one LDG.64: 4 halves = features [tg*4, tg*4+4)
                uint2 hw = *(const uint2*)(g_xh + (size_t)dd[u] * IN_DIM + tg * 4);
                float2 f01 = __half22float2(*(half2*)&hw.x);
                float2 f23 = __half22float2(*(half2*)&hw.y);
                if (i < lim) {                       // predicated add
                    acc.x += f01.x; acc.y += f01.y;
                    acc.z += f23.x; acc.w += f23.y;
                }
            }
        }
#pragma unroll
        for (int off = 4; off < 32; off <<= 1) {
            acc.x += __shfl_xor_sync(0xffffffffu, acc.x, off);
            acc.y += __shfl_xor_sync(0xffffffffu, acc.y, off);
            acc.z += __shfl_xor_sync(0xffffffffu, acc.z, off);
            acc.w += __shfl_xor_sync(0xffffffffu, acc.w, off);
        }
        if (lane < 4) {
            float inv = 1.0f / fmaxf((float)deg, 1.0f);
            float4 xv = ((const float4*)(x + (size_t)node * IN_DIM))[lane];
            uint4 o;
            o.x = f2tf32(xv.x + acc.x * inv);
            o.y = f2tf32(xv.y + acc.y * inv);
            o.z = f2tf32(xv.z + acc.z * inv);
            o.w = f2tf32(xv.w + acc.w * inv);
            ((uint4*)(g_vt + (size_t)node * IN_DIM))[lane] = o;
        }
    }
}

// ---------------------------------------------------------------------------
// MLP: tensor-core 16->64->64 on dense g_vt, hoisted A-fragments,
// last-block finalize + self-clean.
// ---------------------------------------------------------------------------
__global__ void __launch_bounds__(TB) mlp_kernel(
    const float* __restrict__ W1, const float* __restrict__ b1,
    const float* __restrict__ W2, const float* __restrict__ b2,
    const float* __restrict__ Wh, const float* __restrict__ bh,
    float* __restrict__ out, int n) {
    __shared__ unsigned sW1t[IN_DIM * W_STRIDE];
    __shared__ unsigned sW2t[HID * W_STRIDE];
    __shared__ float sb1[HID];
    __shared__ float sb2[HID];
    __shared__ unsigned sv[4][TILE * V_STRIDE];
    __shared__ unsigned sh1[4][TILE * H_STRIDE];
    __shared__ float ssum[HID];
    __shared__ int slast;

    int tid  = threadIdx.x;
    int wid  = tid >> 5;
    int lane = tid & 31;
    int g    = lane >> 2;     // mma groupID (row)
    int tg   = lane & 3;      // mma threadID_in_group

    for (int i = tid; i < IN_DIM * HID; i += TB) {
        int k = i >> 6, nn = i & 63;
        sW1t[k * W_STRIDE + nn] = f2tf32(W1[i]);
    }
    for (int i = tid; i < HID * HID; i += TB) {
        int k = i >> 6, nn = i & 63;
        sW2t[k * W_STRIDE + nn] = f2tf32(W2[i]);
    }
    if (tid < HID) { sb1[tid] = b1[tid]; sb2[tid] = b2[tid]; ssum[tid] = 0.0f; }
    __syncthreads();

    unsigned* svw = sv[wid];
    unsigned* shw = sh1[wid];
    float macc[16];
#pragma unroll
    for (int i = 0; i < 16; i++) macc[i] = 0.0f;

    for (int base = (blockIdx.x * 4 + wid) * TILE; base < n;
         base += GRID2 * 4 * TILE) {

        // ---- load 16x16 v tile from g_vt (coalesced; zero-pad tail) ----
        const unsigned* src = g_vt + (size_t)base * IN_DIM;
#pragma unroll
        for (int j = 0; j < 8; j++) {
            int idx = lane * 8 + j;          // 0..255
            int nl  = idx >> 4;
            int k   = idx & 15;
            unsigned v = (base + nl < n) ? src[idx] : 0u;
            svw[nl * V_STRIDE + k] = v;
        }
        __syncwarp();

        // ---- layer 1: h1[16,64] = relu(v @ W1 + b1), hoisted A-frags ----
        unsigned a1f[2][4];
#pragma unroll
        for (int kt = 0; kt < 2; kt++) {
            int c = kt * 8 + tg;
            a1f[kt][0] = svw[g * V_STRIDE + c];
            a1f[kt][1] = svw[(g + 8) * V_STRIDE + c];
            a1f[kt][2] = svw[g * V_STRIDE + c + 4];
            a1f[kt][3] = svw[(g + 8) * V_STRIDE + c + 4];
        }
#pragma unroll
        for (int nt = 0; nt < 8; nt++) {
            int ce = nt * 8 + 2 * tg;
            float d0 = sb1[ce], d1 = sb1[ce + 1], d2 = d0, d3 = d1;
#pragma unroll
            for (int kt = 0; kt < 2; kt++) {
                unsigned bf0 = sW1t[(kt * 8 + tg) * W_STRIDE + nt * 8 + g];
                unsigned bf1 = sW1t[(kt * 8 + tg + 4) * W_STRIDE + nt * 8 + g];
                mma_tf32(d0, d1, d2, d3,
                         a1f[kt][0], a1f[kt][1], a1f[kt][2], a1f[kt][3], bf0, bf1);
            }
            shw[g * H_STRIDE + ce]           = f2tf32(fmaxf(d0, 0.0f));
            shw[g * H_STRIDE + ce + 1]       = f2tf32(fmaxf(d1, 0.0f));
            shw[(g + 8) * H_STRIDE + ce]     = f2tf32(fmaxf(d2, 0.0f));
            shw[(g + 8) * H_STRIDE + ce + 1] = f2tf32(fmaxf(d3, 0.0f));
        }
        __syncwarp();

        // ---- layer 2 + masked mean accumulation, hoisted A-frags ----
        unsigned a2f[8][4];
#pragma unroll
        for (int kt = 0; kt < 8; kt++) {
            int c = kt * 8 + tg;
            a2f[kt][0] = shw[g * H_STRIDE + c];
            a2f[kt][1] = shw[(g + 8) * H_STRIDE + c];
            a2f[kt][2] = shw[g * H_STRIDE + c + 4];
            a2f[kt][3] = shw[(g + 8) * H_STRIDE + c + 4];
        }
        float mv0 = (base + g     < n) ? 1.0f : 0.0f;
        float mv8 = (base + g + 8 < n) ? 1.0f : 0.0f;
#pragma unroll
        for (int nt = 0; nt < 8; nt++) {
            int ce = nt * 8 + 2 * tg;
            float d0 = sb2[ce], d1 = sb2[ce + 1], d2 = d0, d3 = d1;
#pragma unroll
            for (int kt = 0; kt < 8; kt++) {
                unsigned bf0 = sW2t[(kt * 8 + tg) * W_STRIDE + nt * 8 + g];
                unsigned bf1 = sW2t[(kt * 8 + tg + 4) * W_STRIDE + nt * 8 + g];
                mma_tf32(d0, d1, d2, d3,
                         a2f[kt][0], a2f[kt][1], a2f[kt][2], a2f[kt][3], bf0, bf1);
            }
            macc[2 * nt]     += mv0 * fmaxf(d0, 0.0f) + mv8 * fmaxf(d2, 0.0f);
            macc[2 * nt + 1] += mv0 * fmaxf(d1, 0.0f) + mv8 * fmaxf(d3, 0.0f);
        }
        __syncwarp();
    }

    // reduce mean partials across row-groups; lanes 0-3 hold 2 features x 8
#pragma unroll
    for (int off = 4; off < 32; off <<= 1)
#pragma unroll
        for (int i = 0; i < 16; i++)
            macc[i] += __shfl_xor_sync(0xffffffffu, macc[i], off);
    if (lane < 4) {
#pragma unroll
        for (int nt = 0; nt < 8; nt++) {
            atomicAdd(&ssum[nt * 8 + 2 * lane],     macc[2 * nt]);
            atomicAdd(&ssum[nt * 8 + 2 * lane + 1], macc[2 * nt + 1]);
        }
    }
    __syncthreads();
    if (tid < HID) atomicAdd(&g_hsum[tid], ssum[tid]);

    // ---- last-block finalize: out = tanh(mean @ Wh + bh); clean state ----
    __threadfence();
    if (tid == 0) {
        unsigned t = atomicAdd(&g_done, 1u);
        slast = (t == (unsigned)(gridDim.x - 1)) ? 1 : 0;
    }
    __syncthreads();
    if (slast) {
        __shared__ float red[HID];
        if (tid < HID) red[tid] = (g_hsum[tid] / (float)n) * Wh[tid];
        __syncthreads();
        for (int s = HID / 2; s > 0; s >>= 1) {
            if (tid < s) red[tid] += red[tid + s];
            __syncthreads();
        }
        if (tid == 0) out[0] = tanhf(red[0] + bh[0]);
        if (tid < HID) g_hsum[tid] = 0.0f;    // self-clean for next replay
        if (tid == 0) g_done = 0u;
    }
}

// ---------------------------------------------------------------------------
extern "C" void kernel_launch(void* const* d_in, const int* in_sizes, int n_in,
                              void* d_out, int out_size) {
    const float* x  = (const float*)d_in[0];
    const int*   ei = (const int*)d_in[1];
    const float* W1 = (const float*)d_in[2];
    const float* b1 = (const float*)d_in[3];
    const float* W2 = (const float*)d_in[4];
    const float* b2 = (const float*)d_in[5];
    const float* Wh = (const float*)d_in[6];
    const float* bh = (const float*)d_in[7];
    float* out = (float*)d_out;

    int n = in_sizes[0] / IN_DIM;
    int E = in_sizes[1] / 2;
    int et = (E + 3) / 4;
    if (et < n * (IN_DIM / 2)) et = n * (IN_DIM / 2);   // cover fp16 convert
    int ab = (n + 8 * TILE - 1) / (8 * TILE);           // agg: 8 warps x 16 nodes

    scatter_kernel<<<(et + 255) / 256, 256>>>(ei, x, E, n);
    agg_kernel<<<ab, AGG_TB>>>(x, n);
    mlp_kernel<<<GRID2, TB>>>(W1, b1, W2, b2, Wh, bh, out, n);
}

// round 16
// speedup vs baseline: 2.8436x; 1.0709x over previous
#include <cuda_runtime.h>
#include <cuda_bf16.h>
#include <cuda_fp16.h>
#include <math.h>

// SimpleGNN, 3 launches, linked-list edge binning:
//   scatter: old = atomicExch(&head[s], e+1); next2[e] = {old, dst}
//            (all loads/stores coalesced; only the exch is random)
//            + x -> fp16 table build folded in
//   agg:     thread-per-node chain walk (100k concurrent chains), fp32
//            accumulate of fp16 rows -> v = x + agg/deg -> g_vt (tf32 bits)
//   mlp:     tensor-core (tf32 mma) MLP on dense g_vt + in-kernel finalize
// Self-cleaning for graph replays: agg re-zeros head (same-thread pattern),
// mlp's last block re-zeros hsum/done; next2 fully rewritten each call.
//
// Inputs: x[N*16] f32, edge_index int32 (harness downcast), W1,b1,W2,b2,Wh,bh.
// Output: 1 f32.

#define MAX_NODES 100000
#define MAX_EDGES 3200000
#define HID       64
#define IN_DIM    16
#define TILE      16           // mlp nodes per warp-tile
#define TB        128          // mlp threads per block (4 warps)
#define GRID2     592          // mlp blocks (~4/SM)
#define W_STRIDE  72           // conflict-free B-frag rows
#define H_STRIDE  68
#define V_STRIDE  17

__device__ int      g_head[MAX_NODES];            // zero-init at load; 0 = empty
__device__ int2     g_next2[MAX_EDGES];           // {next_e+1, dst}
__device__ __half   g_xh[MAX_NODES * IN_DIM];     // fp16 x table (3.2 MB)
__device__ unsigned g_vt[MAX_NODES * IN_DIM];     // v in tf32 bits (6.4 MB)
__device__ float    g_hsum[HID];                  // zero-init at load
__device__ unsigned g_done;                       // zero-init at load

__device__ __forceinline__ unsigned f2tf32(float f) {
    unsigned r; asm("cvt.rna.tf32.f32 %0, %1;" : "=r"(r) : "f"(f)); return r;
}

__device__ __forceinline__ void mma_tf32(float& d0, float& d1, float& d2, float& d3,
                                         unsigned a0, unsigned a1, unsigned a2, unsigned a3,
                                         unsigned b0, unsigned b1) {
    asm volatile(
        "mma.sync.aligned.m16n8k8.row.col.f32.tf32.tf32.f32 "
        "{%0,%1,%2,%3}, {%4,%5,%6,%7}, {%8,%9}, {%0,%1,%2,%3};"
        : "+f"(d0), "+f"(d1), "+f"(d2), "+f"(d3)
        : "r"(a0), "r"(a1), "r"(a2), "r"(a3), "r"(b0), "r"(b1));
}

// ---------------------------------------------------------------------------
// Scatter (linked list) + x->fp16 conversion. Strided edge assignment keeps
// ei loads AND next2 stores coalesced; only the exch is a random L2 op.
// ---------------------------------------------------------------------------
__global__ void scatter_kernel(const int* __restrict__ ei,
                               const float* __restrict__ x,
                               int E, int n, int T) {
    int t = blockIdx.x * blockDim.x + threadIdx.x;

    // fp16 table build (coalesced, independent of edge work)
    int nh2 = n * (IN_DIM / 2);
    if (t < nh2) {
        float2 f = ((const float2*)x)[t];
        ((half2*)g_xh)[t] = __floats2half2_rn(f.x, f.y);
    }

#pragma unroll
    for (int j = 0; j < 4; j++) {
        int e = t + j * T;                 // strided: coalesced ld/st
        if (e < E) {
            int s = ei[e];
            int d = ei[e + E];
            if ((unsigned)s < (unsigned)n) {
                int old = atomicExch(&g_head[s], e + 1);
                g_next2[e] = make_int2(old, d);
            }
        }
    }
}

// ---------------------------------------------------------------------------
// Aggregation: one thread per node walks its chain. fp32 accumulation of
// fp16 rows; writes v = x + agg/deg as tf32 bits to g_vt.
// ---------------------------------------------------------------------------
__global__ void __launch_bounds__(256) agg_kernel(const float* __restrict__ x,
                                                  int n) {
    int node = blockIdx.x * blockDim.x + threadIdx.x;
    if (node >= n) return;

    int e = g_head[node];
    g_head[node] = 0;                      // same-thread clean: order-safe

    float acc[IN_DIM];
#pragma unroll
    for (int k = 0; k < IN_DIM; k++) acc[k] = 0.0f;
    int deg = 0;

    while (e) {
        int2 nd = g_next2[e - 1];
        e = nd.x;
        const uint4* row = (const uint4*)(g_xh + (size_t)nd.y * IN_DIM);
        uint4 r0 = row[0];                 // 16 halves = 32B = 1 sector
        uint4 r1 = row[1];
        float2 f;
        f = __half22float2(*(half2*)&r0.x); acc[0] += f.x;  acc[1] += f.y;
        f = __half22float2(*(half2*)&r0.y); acc[2] += f.x;  acc[3] += f.y;
        f = __half22float2(*(half2*)&r0.z); acc[4] += f.x;  acc[5] += f.y;
        f = __half22float2(*(half2*)&r0.w); acc[6] += f.x;  acc[7] += f.y;
        f = __half22float2(*(half2*)&r1.x); acc[8] += f.x;  acc[9] += f.y;
        f = __half22float2(*(half2*)&r1.y); acc[10] += f.x; acc[11] += f.y;
        f = __half22float2(*(half2*)&r1.z); acc[12] += f.x; acc[13] += f.y;
        f = __half22float2(*(half2*)&r1.w); acc[14] += f.x; acc[15] += f.y;
        deg++;
    }

    float inv = 1.0f / fmaxf((float)deg, 1.0f);
    const float4* xr = (const float4*)(x + (size_t)node * IN_DIM);
    unsigned* vp = g_vt + (size_t)node * IN_DIM;
#pragma unroll
    for (int q = 0; q < 4; q++) {
        float4 xv = xr[q];
        uint4 o;
        o.x = f2tf32(xv.x + acc[q * 4 + 0] * inv);
        o.y = f2tf32(xv.y + acc[q * 4 + 1] * inv);
        o.z = f2tf32(xv.z + acc[q * 4 + 2] * inv);
        o.w = f2tf32(xv.w + acc[q * 4 + 3] * inv);
        ((uint4*)vp)[q] = o;
    }
}

// ---------------------------------------------------------------------------
// MLP: tensor-core 16->64->64 on dense g_vt, hoisted A-fragments,
// last-block finalize + self-clean.
// ---------------------------------------------------------------------------
__global__ void __launch_bounds__(TB) mlp_kernel(
    const float* __restrict__ W1, const float* __restrict__ b1,
    const float* __restrict__ W2, const float* __restrict__ b2,
    const float* __restrict__ Wh, const float* __restrict__ bh,
    float* __restrict__ out, int n) {
    __shared__ unsigned sW1t[IN_DIM * W_STRIDE];
    __shared__ unsigned sW2t[HID * W_STRIDE];
    __shared__ float sb1[HID];
    __shared__ float sb2[HID];
    __shared__ unsigned sv[4][TILE * V_STRIDE];
    __shared__ unsigned sh1[4][TILE * H_STRIDE];
    __shared__ float ssum[HID];
    __shared__ int slast;

    int tid  = threadIdx.x;
    int wid  = tid >> 5;
    int lane = tid & 31;
    int g    = lane >> 2;     // mma groupID (row)
    int tg   = lane & 3;      // mma threadID_in_group

    for (int i = tid; i < IN_DIM * HID; i += TB) {
        int k = i >> 6, nn = i & 63;
        sW1t[k * W_STRIDE + nn] = f2tf32(W1[i]);
    }
    for (int i = tid; i < HID * HID; i += TB) {
        int k = i >> 6, nn = i & 63;
        sW2t[k * W_STRIDE + nn] = f2tf32(W2[i]);
    }
    if (tid < HID) { sb1[tid] = b1[tid]; sb2[tid] = b2[tid]; ssum[tid] = 0.0f; }
    __syncthreads();

    unsigned* svw = sv[wid];
    unsigned* shw = sh1[wid];
    float macc[16];
#pragma unroll
    for (int i = 0; i < 16; i++) macc[i] = 0.0f;

    for (int base = (blockIdx.x * 4 + wid) * TILE; base < n;
         base += GRID2 * 4 * TILE) {

        // ---- load 16x16 v tile from g_vt (coalesced; zero-pad tail) ----
        const unsigned* src = g_vt + (size_t)base * IN_DIM;
#pragma unroll
        for (int j = 0; j < 8; j++) {
            int idx = lane * 8 + j;          // 0..255
            int nl  = idx >> 4;
            int k   = idx & 15;
            unsigned v = (base + nl < n) ? src[idx] : 0u;
            svw[nl * V_STRIDE + k] = v;
        }
        __syncwarp();

        // ---- layer 1: h1[16,64] = relu(v @ W1 + b1), hoisted A-frags ----
        unsigned a1f[2][4];
#pragma unroll
        for (int kt = 0; kt < 2; kt++) {
            int c = kt * 8 + tg;
            a1f[kt][0] = svw[g * V_STRIDE + c];
            a1f[kt][1] = svw[(g + 8) * V_STRIDE + c];
            a1f[kt][2] = svw[g * V_STRIDE + c + 4];
            a1f[kt][3] = svw[(g + 8) * V_STRIDE + c + 4];
        }
#pragma unroll
        for (int nt = 0; nt < 8; nt++) {
            int ce = nt * 8 + 2 * tg;
            float d0 = sb1[ce], d1 = sb1[ce + 1], d2 = d0, d3 = d1;
#pragma unroll
            for (int kt = 0; kt < 2; kt++) {
                unsigned bf0 = sW1t[(kt * 8 + tg) * W_STRIDE + nt * 8 + g];
                unsigned bf1 = sW1t[(kt * 8 + tg + 4) * W_STRIDE + nt * 8 + g];
                mma_tf32(d0, d1, d2, d3,
                         a1f[kt][0], a1f[kt][1], a1f[kt][2], a1f[kt][3], bf0, bf1);
            }
            shw[g * H_STRIDE + ce]           = f2tf32(fmaxf(d0, 0.0f));
            shw[g * H_STRIDE + ce + 1]       = f2tf32(fmaxf(d1, 0.0f));
            shw[(g + 8) * H_STRIDE + ce]     = f2tf32(fmaxf(d2, 0.0f));
            shw[(g + 8) * H_STRIDE + ce + 1] = f2tf32(fmaxf(d3, 0.0f));
        }
        __syncwarp();

        // ---- layer 2 + masked mean accumulation, hoisted A-frags ----
        unsigned a2f[8][4];
#pragma unroll
        for (int kt = 0; kt < 8; kt++) {
            int c = kt * 8 + tg;
            a2f[kt][0] = shw[g * H_STRIDE + c];
            a2f[kt][1] = shw[(g + 8) * H_STRIDE + c];
            a2f[kt][2] = shw[g * H_STRIDE + c + 4];
            a2f[kt][3] = shw[(g + 8) * H_STRIDE + c + 4];
        }
        float mv0 = (base + g     < n) ? 1.0f : 0.0f;
        float mv8 = (base + g + 8 < n) ? 1.0f : 0.0f;
#pragma unroll
        for (int nt = 0; nt < 8; nt++) {
            int ce = nt * 8 + 2 * tg;
            float d0 = sb2[ce], d1 = sb2[ce + 1], d2 = d0, d3 = d1;
#pragma unroll
            for (int kt = 0; kt < 8; kt++) {
                unsigned bf0 = sW2t[(kt * 8 + tg) * W_STRIDE + nt * 8 + g];
                unsigned bf1 = sW2t[(kt * 8 + tg + 4) * W_STRIDE + nt * 8 + g];
                mma_tf32(d0, d1, d2, d3,
                         a2f[kt][0], a2f[kt][1], a2f[kt][2], a2f[kt][3], bf0, bf1);
            }
            macc[2 * nt]     += mv0 * fmaxf(d0, 0.0f) + mv8 * fmaxf(d2, 0.0f);
            macc[2 * nt + 1] += mv0 * fmaxf(d1, 0.0f) + mv8 * fmaxf(d3, 0.0f);
        }
        __syncwarp();
    }

    // reduce mean partials across row-groups; lanes 0-3 hold 2 features x 8
#pragma unroll
    for (int off = 4; off < 32; off <<= 1)
#pragma unroll
        for (int i = 0; i < 16; i++)
            macc[i] += __shfl_xor_sync(0xffffffffu, macc[i], off);
    if (lane < 4) {
#pragma unroll
        for (int nt = 0; nt < 8; nt++) {
            atomicAdd(&ssum[nt * 8 + 2 * lane],     macc[2 * nt]);
            atomicAdd(&ssum[nt * 8 + 2 * lane + 1], macc[2 * nt + 1]);
        }
    }
    __syncthreads();
    if (tid < HID) atomicAdd(&g_hsum[tid], ssum[tid]);

    // ---- last-block finalize: out = tanh(mean @ Wh + bh); clean state ----
    __threadfence();
    if (tid == 0) {
        unsigned t = atomicAdd(&g_done, 1u);
        slast = (t == (unsigned)(gridDim.x - 1)) ? 1 : 0;
    }
    __syncthreads();
    if (slast) {
        __shared__ float red[HID];
        if (tid < HID) red[tid] = (g_hsum[tid] / (float)n) * Wh[tid];
        __syncthreads();
        for (int s = HID / 2; s > 0; s >>= 1) {
            if (tid < s) red[tid] += red[tid + s];
            __syncthreads();
        }
        if (tid == 0) out[0] = tanhf(red[0] + bh[0]);
        if (tid < HID) g_hsum[tid] = 0.0f;    // self-clean for next replay
        if (tid == 0) g_done = 0u;
    }
}

// ---------------------------------------------------------------------------
extern "C" void kernel_launch(void* const* d_in, const int* in_sizes, int n_in,
                              void* d_out, int out_size) {
    const float* x  = (const float*)d_in[0];
    const int*   ei = (const int*)d_in[1];
    const float* W1 = (const float*)d_in[2];
    const float* b1 = (const float*)d_in[3];
    const float* W2 = (const float*)d_in[4];
    const float* b2 = (const float*)d_in[5];
    const float* Wh = (const float*)d_in[6];
    const float* bh = (const float*)d_in[7];
    float* out = (float*)d_out;

    int n = in_sizes[0] / IN_DIM;
    int E = in_sizes[1] / 2;
    int T = (E + 3) / 4;                   // scatter threads (4 strided edges)
    int st = T;
    if (st < n * (IN_DIM / 2)) st = n * (IN_DIM / 2);   // cover fp16 convert

    scatter_kernel<<<(st + 255) / 256, 256>>>(ei, x, E, n, T);
    agg_kernel<<<(n + 255) / 256, 256>>>(x, n);
    mlp_kernel<<<GRID2, TB>>>(W1, b1, W2, b2, Wh, bh, out, n);
}

// round 17
// speedup vs baseline: 2.9502x; 1.0375x over previous
#include <cuda_runtime.h>
#include <cuda_bf16.h>
#include <cuda_fp16.h>
#include <cuda_fp8.h>
#include <math.h>

// SimpleGNN, 3 launches, linked-list edge binning + fp8 neighbor table:
//   scatter: old = atomicExch(&head[s], e+1); next2[e] = {old, dst}
//            + x -> fp8 (e4m3) table g_x8 (16B/row) folded in
//   agg:     thread-per-node chain walk; per edge ONE LDG.128 row load,
//            fp8->half2 decode, half2 accumulate -> v = x + agg/deg -> g_vt
//   mlp:     tensor-core (tf32 mma) MLP on dense g_vt + in-kernel finalize
// Self-cleaning for graph replays: agg re-zeros head (same-thread pattern),
// mlp's last block re-zeros hsum/done; next2/g_x8 fully rewritten each call.
//
// Inputs: x[N*16] f32, edge_index int32 (harness downcast), W1,b1,W2,b2,Wh,bh.
// Output: 1 f32.

#define MAX_NODES 100000
#define MAX_EDGES 3200000
#define HID       64
#define IN_DIM    16
#define TILE      16           // mlp nodes per warp-tile
#define TB        128          // mlp threads per block (4 warps)
#define GRID2     592          // mlp blocks (~4/SM)
#define W_STRIDE  72           // conflict-free B-frag rows
#define H_STRIDE  68
#define V_STRIDE  17

__device__ int      g_head[MAX_NODES];            // zero-init at load; 0 = empty
__device__ int2     g_next2[MAX_EDGES];           // {next_e+1, dst}
__device__ uint4    g_x8[MAX_NODES];              // fp8 e4m3 rows, 16B each
__device__ unsigned g_vt[MAX_NODES * IN_DIM];     // v in tf32 bits (6.4 MB)
__device__ float    g_hsum[HID];                  // zero-init at load
__device__ unsigned g_done;                       // zero-init at load

__device__ __forceinline__ unsigned f2tf32(float f) {
    unsigned r; asm("cvt.rna.tf32.f32 %0, %1;" : "=r"(r) : "f"(f)); return r;
}

__device__ __forceinline__ void mma_tf32(float& d0, float& d1, float& d2, float& d3,
                                         unsigned a0, unsigned a1, unsigned a2, unsigned a3,
                                         unsigned b0, unsigned b1) {
    asm volatile(
        "mma.sync.aligned.m16n8k8.row.col.f32.tf32.tf32.f32 "
        "{%0,%1,%2,%3}, {%4,%5,%6,%7}, {%8,%9}, {%0,%1,%2,%3};"
        : "+f"(d0), "+f"(d1), "+f"(d2), "+f"(d3)
        : "r"(a0), "r"(a1), "r"(a2), "r"(a3), "r"(b0), "r"(b1));
}

__device__ __forceinline__ unsigned pack_fp8x4(float4 v) {
    __nv_fp8x2_storage_t lo =
        __nv_cvt_float2_to_fp8x2(make_float2(v.x, v.y), __NV_SATFINITE, __NV_E4M3);
    __nv_fp8x2_storage_t hi =
        __nv_cvt_float2_to_fp8x2(make_float2(v.z, v.w), __NV_SATFINITE, __NV_E4M3);
    return (unsigned)lo | ((unsigned)hi << 16);
}

__device__ __forceinline__ void acc_fp8x4(unsigned w, __half2& h01, __half2& h23) {
    __half2_raw r0 = __nv_cvt_fp8x2_to_halfraw2((__nv_fp8x2_storage_t)(w & 0xffffu),
                                                __NV_E4M3);
    __half2_raw r1 = __nv_cvt_fp8x2_to_halfraw2((__nv_fp8x2_storage_t)(w >> 16),
                                                __NV_E4M3);
    h01 = __hadd2(h01, *(__half2*)&r0);
    h23 = __hadd2(h23, *(__half2*)&r1);
}

// ---------------------------------------------------------------------------
// Scatter (linked list) + x->fp8 table. Strided edge assignment keeps ei
// loads AND next2 stores coalesced; only the exch is a random L2 op.
// ---------------------------------------------------------------------------
__global__ void scatter_kernel(const int* __restrict__ ei,
                               const float* __restrict__ x,
                               int E, int n, int T) {
    int t = blockIdx.x * blockDim.x + threadIdx.x;

    // fp8 table build: thread t converts node t's row (64B read, 16B write)
    if (t < n) {
        const float4* xr = (const float4*)(x + (size_t)t * IN_DIM);
        uint4 o;
        o.x = pack_fp8x4(xr[0]);
        o.y = pack_fp8x4(xr[1]);
        o.z = pack_fp8x4(xr[2]);
        o.w = pack_fp8x4(xr[3]);
        g_x8[t] = o;
    }

#pragma unroll
    for (int j = 0; j < 4; j++) {
        int e = t + j * T;                 // strided: coalesced ld/st
        if (e < E) {
            int s = ei[e];
            int d = ei[e + E];
            if ((unsigned)s < (unsigned)n) {
                int old = atomicExch(&g_head[s], e + 1);
                g_next2[e] = make_int2(old, d);
            }
        }
    }
}

// ---------------------------------------------------------------------------
// Aggregation: one thread per node walks its chain. One LDG.128 per edge
// (fp8 row), half2 accumulation; writes v = x + agg/deg (tf32 bits) to g_vt.
// ---------------------------------------------------------------------------
__global__ void __launch_bounds__(256) agg_kernel(const float* __restrict__ x,
                                                  int n) {
    int node = blockIdx.x * blockDim.x + threadIdx.x;
    if (node >= n) return;

    int e = g_head[node];
    g_head[node] = 0;                      // same-thread clean: order-safe

    __half2 h[8];
#pragma unroll
    for (int k = 0; k < 8; k++) h[k] = __half2(__float2half(0.f), __float2half(0.f));
    int deg = 0;

    while (e) {
        int2 nd = g_next2[e - 1];
        e = nd.x;
        uint4 row = g_x8[nd.y];            // 16B = one LDG.128
        acc_fp8x4(row.x, h[0], h[1]);
        acc_fp8x4(row.y, h[2], h[3]);
        acc_fp8x4(row.z, h[4], h[5]);
        acc_fp8x4(row.w, h[6], h[7]);
        deg++;
    }

    float acc[IN_DIM];
#pragma unroll
    for (int k = 0; k < 8; k++) {
        float2 f = __half22float2(h[k]);
        acc[k * 2] = f.x;
        acc[k * 2 + 1] = f.y;
    }

    float inv = 1.0f / fmaxf((float)deg, 1.0f);
    const float4* xr = (const float4*)(x + (size_t)node * IN_DIM);
    unsigned* vp = g_vt + (size_t)node * IN_DIM;
#pragma unroll
    for (int q = 0; q < 4; q++) {
        float4 xv = xr[q];
        uint4 o;
        o.x = f2tf32(xv.x + acc[q * 4 + 0] * inv);
        o.y = f2tf32(xv.y + acc[q * 4 + 1] * inv);
        o.z = f2tf32(xv.z + acc[q * 4 + 2] * inv);
        o.w = f2tf32(xv.w + acc[q * 4 + 3] * inv);
        ((uint4*)vp)[q] = o;
    }
}

// ---------------------------------------------------------------------------
// MLP: tensor-core 16->64->64 on dense g_vt, hoisted A-fragments,
// last-block finalize + self-clean.
// ---------------------------------------------------------------------------
__global__ void __launch_bounds__(TB) mlp_kernel(
    const float* __restrict__ W1, const float* __restrict__ b1,
    const float* __restrict__ W2, const float* __restrict__ b2,
    const float* __restrict__ Wh, const float* __restrict__ bh,
    float* __restrict__ out, int n) {
    __shared__ unsigned sW1t[IN_DIM * W_STRIDE];
    __shared__ unsigned sW2t[HID * W_STRIDE];
    __shared__ float sb1[HID];
    __shared__ float sb2[HID];
    __shared__ unsigned sv[4][TILE * V_STRIDE];
    __shared__ unsigned sh1[4][TILE * H_STRIDE];
    __shared__ float ssum[HID];
    __shared__ int slast;

    int tid  = threadIdx.x;
    int wid  = tid >> 5;
    int lane = tid & 31;
    int g    = lane >> 2;     // mma groupID (row)
    int tg   = lane & 3;      // mma threadID_in_group

    for (int i = tid; i < IN_DIM * HID; i += TB) {
        int k = i >> 6, nn = i & 63;
        sW1t[k * W_STRIDE + nn] = f2tf32(W1[i]);
    }
    for (int i = tid; i < HID * HID; i += TB) {
        int k = i >> 6, nn = i & 63;
        sW2t[k * W_STRIDE + nn] = f2tf32(W2[i]);
    }
    if (tid < HID) { sb1[tid] = b1[tid]; sb2[tid] = b2[tid]; ssum[tid] = 0.0f; }
    __syncthreads();

    unsigned* svw = sv[wid];
    unsigned* shw = sh1[wid];
    float macc[16];
#pragma unroll
    for (int i = 0; i < 16; i++) macc[i] = 0.0f;

    for (int base = (blockIdx.x * 4 + wid) * TILE; base < n;
         base += GRID2 * 4 * TILE) {

        // ---- load 16x16 v tile from g_vt (coalesced; zero-pad tail) ----
        const unsigned* src = g_vt + (size_t)base * IN_DIM;
#pragma unroll
        for (int j = 0; j < 8; j++) {
            int idx = lane * 8 + j;          // 0..255
            int nl  = idx >> 4;
            int k   = idx & 15;
            unsigned v = (base + nl < n) ? src[idx] : 0u;
            svw[nl * V_STRIDE + k] = v;
        }
        __syncwarp();

        // ---- layer 1: h1[16,64] = relu(v @ W1 + b1), hoisted A-frags ----
        unsigned a1f[2][4];
#pragma unroll
        for (int kt = 0; kt < 2; kt++) {
            int c = kt * 8 + tg;
            a1f[kt][0] = svw[g * V_STRIDE + c];
            a1f[kt][1] = svw[(g + 8) * V_STRIDE + c];
            a1f[kt][2] = svw[g * V_STRIDE + c + 4];
            a1f[kt][3] = svw[(g + 8) * V_STRIDE + c + 4];
        }
#pragma unroll
        for (int nt = 0; nt < 8; nt++) {
            int ce = nt * 8 + 2 * tg;
            float d0 = sb1[ce], d1 = sb1[ce + 1], d2 = d0, d3 = d1;
#pragma unroll
            for (int kt = 0; kt < 2; kt++) {
                unsigned bf0 = sW1t[(kt * 8 + tg) * W_STRIDE + nt * 8 + g];
                unsigned bf1 = sW1t[(kt * 8 + tg + 4) * W_STRIDE + nt * 8 + g];
                mma_tf32(d0, d1, d2, d3,
                         a1f[kt][0], a1f[kt][1], a1f[kt][2], a1f[kt][3], bf0, bf1);
            }
            shw[g * H_STRIDE + ce]           = f2tf32(fmaxf(d0, 0.0f));
            shw[g * H_STRIDE + ce + 1]       = f2tf32(fmaxf(d1, 0.0f));
            shw[(g + 8) * H_STRIDE + ce]     = f2tf32(fmaxf(d2, 0.0f));
            shw[(g + 8) * H_STRIDE + ce + 1] = f2tf32(fmaxf(d3, 0.0f));
        }
        __syncwarp();

        // ---- layer 2 + masked mean accumulation, hoisted A-frags ----
        unsigned a2f[8][4];
#pragma unroll
        for (int kt = 0; kt < 8; kt++) {
            int c = kt * 8 + tg;
            a2f[kt][0] = shw[g * H_STRIDE + c];
            a2f[kt][1] = shw[(g + 8) * H_STRIDE + c];
            a2f[kt][2] = shw[g * H_STRIDE + c + 4];
            a2f[kt][3] = shw[(g + 8) * H_STRIDE + c + 4];
        }
        float mv0 = (base + g     < n) ? 1.0f : 0.0f;
        float mv8 = (base + g + 8 < n) ? 1.0f : 0.0f;
#pragma unroll
        for (int nt = 0; nt < 8; nt++) {
            int ce = nt * 8 + 2 * tg;
            float d0 = sb2[ce], d1 = sb2[ce + 1], d2 = d0, d3 = d1;
#pragma unroll
            for (int kt = 0; kt < 8; kt++) {
                unsigned bf0 = sW2t[(kt * 8 + tg) * W_STRIDE + nt * 8 + g];
                unsigned bf1 = sW2t[(kt * 8 + tg + 4) * W_STRIDE + nt * 8 + g];
                mma_tf32(d0, d1, d2, d3,
                         a2f[kt][0], a2f[kt][1], a2f[kt][2], a2f[kt][3], bf0, bf1);
            }
            macc[2 * nt]     += mv0 * fmaxf(d0, 0.0f) + mv8 * fmaxf(d2, 0.0f);
            macc[2 * nt + 1] += mv0 * fmaxf(d1, 0.0f) + mv8 * fmaxf(d3, 0.0f);
        }
        __syncwarp();
    }

    // reduce mean partials across row-groups; lanes 0-3 hold 2 features x 8
#pragma unroll
    for (int off = 4; off < 32; off <<= 1)
#pragma unroll
        for (int i = 0; i < 16; i++)
            macc[i] += __shfl_xor_sync(0xffffffffu, macc[i], off);
    if (lane < 4) {
#pragma unroll
        for (int nt = 0; nt < 8; nt++) {
            atomicAdd(&ssum[nt * 8 + 2 * lane],     macc[2 * nt]);
            atomicAdd(&ssum[nt * 8 + 2 * lane + 1], macc[2 * nt + 1]);
        }
    }
    __syncthreads();
    if (tid < HID) atomicAdd(&g_hsum[tid], ssum[tid]);

    // ---- last-block finalize: out = tanh(mean @ Wh + bh); clean state ----
    __threadfence();
    if (tid == 0) {
        unsigned t = atomicAdd(&g_done, 1u);
        slast = (t == (unsigned)(gridDim.x - 1)) ? 1 : 0;
    }
    __syncthreads();
    if (slast) {
        __shared__ float red[HID];
        if (tid < HID) red[tid] = (g_hsum[tid] / (float)n) * Wh[tid];
        __syncthreads();
        for (int s = HID / 2; s > 0; s >>= 1) {
            if (tid < s) red[tid] += red[tid + s];
            __syncthreads();
        }
        if (tid == 0) out[0] = tanhf(red[0] + bh[0]);
        if (tid < HID) g_hsum[tid] = 0.0f;    // self-clean for next replay
        if (tid == 0) g_done = 0u;
    }
}

// ---------------------------------------------------------------------------
extern "C" void kernel_launch(void* const* d_in, const int* in_sizes, int n_in,
                              void* d_out, int out_size) {
    const float* x  = (const float*)d_in[0];
    const int*   ei = (const int*)d_in[1];
    const float* W1 = (const float*)d_in[2];
    const float* b1 = (const float*)d_in[3];
    const float* W2 = (const float*)d_in[4];
    const float* b2 = (const float*)d_in[5];
    const float* Wh = (const float*)d_in[6];
    const float* bh = (const float*)d_in[7];
    float* out = (float*)d_out;

    int n = in_sizes[0] / IN_DIM;
    int E = in_sizes[1] / 2;
    int T = (E + 3) / 4;                   // scatter threads (4 strided edges)
    int st = (T > n) ? T : n;              // also cover fp8 convert

    scatter_kernel<<<(st + 255) / 256, 256>>>(ei, x, E, n, T);
    agg_kernel<<<(n + 255) / 256, 256>>>(x, n);
    mlp_kernel<<<GRID2, TB>>>(W1, b1, W2, b2, Wh, bh, out, n);
}